// round 1
// baseline (speedup 1.0000x reference)
#include <cuda_runtime.h>

#define T 1024
#define BATCH 64

// Scratch (device globals — no allocations allowed)
__device__ float d_A1sm[3][1032];   // softmax(A1) + 8 zero pads
__device__ float d_tail[3][1024];   // (1-beta_a) + sig(-10)*suffix(A1sm, T-i)
__device__ float d_A2sm[3][1024];
__device__ float d_A4sm[3];
__device__ float d_S[3][BATCH];     // per-branch, per-batch  sum_i A2sm[i]*(1-act1[i])

__device__ __forceinline__ float clamp01(float v) { return fminf(fmaxf(v, 0.f), 1.f); }

// ---------------------------------------------------------------------------
// Setup: softmaxes, suffix scan of A1sm, tail terms. 1 block x 1024 threads.
// ---------------------------------------------------------------------------
__device__ __forceinline__ float blockReduceMax1024(float v, float* sh32) {
    int w = threadIdx.x >> 5, l = threadIdx.x & 31;
    #pragma unroll
    for (int off = 16; off; off >>= 1) v = fmaxf(v, __shfl_xor_sync(0xffffffffu, v, off));
    if (l == 0) sh32[w] = v;
    __syncthreads();
    if (w == 0) {
        float x = sh32[l];
        #pragma unroll
        for (int off = 16; off; off >>= 1) x = fmaxf(x, __shfl_xor_sync(0xffffffffu, x, off));
        if (l == 0) sh32[0] = x;
    }
    __syncthreads();
    float r = sh32[0];
    __syncthreads();
    return r;
}

__device__ __forceinline__ float blockReduceSum1024(float v, float* sh32) {
    int w = threadIdx.x >> 5, l = threadIdx.x & 31;
    #pragma unroll
    for (int off = 16; off; off >>= 1) v += __shfl_xor_sync(0xffffffffu, v, off);
    if (l == 0) sh32[w] = v;
    __syncthreads();
    if (w == 0) {
        float x = sh32[l];
        #pragma unroll
        for (int off = 16; off; off >>= 1) x += __shfl_xor_sync(0xffffffffu, x, off);
        if (l == 0) sh32[0] = x;
    }
    __syncthreads();
    float r = sh32[0];
    __syncthreads();
    return r;
}

__global__ void __launch_bounds__(1024) setup_kernel(
    const float* __restrict__ A1a, const float* __restrict__ A1b, const float* __restrict__ A1c,
    const float* __restrict__ A2a, const float* __restrict__ A2b, const float* __restrict__ A2c,
    const float* __restrict__ A4,
    const float* __restrict__ ba1, const float* __restrict__ ba2, const float* __restrict__ ba3)
{
    __shared__ float sh[1024];
    __shared__ float sh32[32];
    __shared__ float swoff[32];
    int t = threadIdx.x;
    int w = t >> 5, l = t & 31;
    const float* A1p[3] = {A1a, A1b, A1c};
    const float* A2p[3] = {A2a, A2b, A2c};
    const float* bap[3] = {ba1, ba2, ba3};
    const float sig10 = 1.f / (1.f + expf(10.f));

    for (int br = 0; br < 3; br++) {
        // ---- softmax(A1) over T ----
        float v = A1p[br][t];
        float m = blockReduceMax1024(v, sh32);
        float e = expf(v - m);
        float ssum = blockReduceSum1024(e, sh32);
        float a1 = e / ssum;
        d_A1sm[br][t] = a1;
        if (t < 8) d_A1sm[br][1024 + t] = 0.f;

        // ---- inclusive suffix scan of a1: Ssuf[t] = sum_{j>=t} a1[j] ----
        float s = a1;
        #pragma unroll
        for (int off = 1; off < 32; off <<= 1) {
            float o = __shfl_down_sync(0xffffffffu, s, off);
            if (l + off < 32) s += o;
        }
        // warp totals
        if (l == 0) sh32[w] = s;   // s at lane 0 == warp sum
        __syncthreads();
        if (w == 0) {
            float x = sh32[l];
            float inc = x;
            #pragma unroll
            for (int off = 1; off < 32; off <<= 1) {
                float o = __shfl_down_sync(0xffffffffu, inc, off);
                if (l + off < 32) inc += o;
            }
            // exclusive suffix over warps: what warps AFTER mine contribute
            float excl = __shfl_down_sync(0xffffffffu, inc, 1);
            if (l == 31) excl = 0.f;
            swoff[l] = excl;
        }
        __syncthreads();
        float Ssuf_t = s + swoff[w];
        sh[t] = Ssuf_t;
        __syncthreads();
        float ba = bap[br][0];
        float ssuf_for_i = (t == 0) ? 0.f : sh[1024 - t];   // Ssuf[T - i], i = t
        d_tail[br][t] = (1.f - ba) + sig10 * ssuf_for_i;
        __syncthreads();

        // ---- softmax(A2) over T ----
        float v2 = A2p[br][t];
        float m2 = blockReduceMax1024(v2, sh32);
        float e2 = expf(v2 - m2);
        float s2 = blockReduceSum1024(e2, sh32);
        d_A2sm[br][t] = e2 / s2;
        __syncthreads();
    }

    if (t == 0) {
        float m = fmaxf(A4[0], fmaxf(A4[1], A4[2]));
        float e0 = expf(A4[0] - m), e1 = expf(A4[1] - m), e2 = expf(A4[2] - m);
        float s = e0 + e1 + e2;
        d_A4sm[0] = e0 / s; d_A4sm[1] = e1 / s; d_A4sm[2] = e2 / s;
    }
}

// ---------------------------------------------------------------------------
// Main correlation kernel. 192 blocks (branch,b) x 256 threads.
// Thread owns a low quad i=[4q,4q+3] and mirrored high quad i=[1020-4q .. +3];
// threads t>=128 take the second half of each j range (balanced j-split).
// ---------------------------------------------------------------------------
__device__ __forceinline__ void corr_loop(const float* __restrict__ sA,
                                          const float* __restrict__ g,
                                          int jb, int je, float* acc)
{
    if (jb >= je) return;
    float4 w = *(const float4*)(g + jb);
    for (int j = jb; j < je; j += 8) {
        float4 a0 = *(const float4*)(sA + j);
        float4 v  = *(const float4*)(g + j + 4);
        acc[0] = fmaf(a0.x, w.x, acc[0]); acc[1] = fmaf(a0.x, w.y, acc[1]);
        acc[2] = fmaf(a0.x, w.z, acc[2]); acc[3] = fmaf(a0.x, w.w, acc[3]);
        acc[0] = fmaf(a0.y, w.y, acc[0]); acc[1] = fmaf(a0.y, w.z, acc[1]);
        acc[2] = fmaf(a0.y, w.w, acc[2]); acc[3] = fmaf(a0.y, v.x, acc[3]);
        acc[0] = fmaf(a0.z, w.z, acc[0]); acc[1] = fmaf(a0.z, w.w, acc[1]);
        acc[2] = fmaf(a0.z, v.x, acc[2]); acc[3] = fmaf(a0.z, v.y, acc[3]);
        acc[0] = fmaf(a0.w, w.w, acc[0]); acc[1] = fmaf(a0.w, v.x, acc[1]);
        acc[2] = fmaf(a0.w, v.y, acc[2]); acc[3] = fmaf(a0.w, v.z, acc[3]);
        float4 a1 = *(const float4*)(sA + j + 4);
        float4 u  = *(const float4*)(g + j + 8);
        acc[0] = fmaf(a1.x, v.x, acc[0]); acc[1] = fmaf(a1.x, v.y, acc[1]);
        acc[2] = fmaf(a1.x, v.z, acc[2]); acc[3] = fmaf(a1.x, v.w, acc[3]);
        acc[0] = fmaf(a1.y, v.y, acc[0]); acc[1] = fmaf(a1.y, v.z, acc[1]);
        acc[2] = fmaf(a1.y, v.w, acc[2]); acc[3] = fmaf(a1.y, u.x, acc[3]);
        acc[0] = fmaf(a1.z, v.z, acc[0]); acc[1] = fmaf(a1.z, v.w, acc[1]);
        acc[2] = fmaf(a1.z, u.x, acc[2]); acc[3] = fmaf(a1.z, u.y, acc[3]);
        acc[0] = fmaf(a1.w, v.w, acc[0]); acc[1] = fmaf(a1.w, u.x, acc[1]);
        acc[2] = fmaf(a1.w, u.y, acc[2]); acc[3] = fmaf(a1.w, u.z, acc[3]);
        w = u;
    }
}

__global__ void __launch_bounds__(256) corr_kernel(
    const float* __restrict__ x1, const float* __restrict__ x2, const float* __restrict__ x3,
    const float* __restrict__ t1, const float* __restrict__ b1,
    const float* __restrict__ t2, const float* __restrict__ b2,
    const float* __restrict__ t3, const float* __restrict__ b3)
{
    __shared__ __align__(16) float sA[1032];
    __shared__ __align__(16) float sG[1040];
    __shared__ float sP[2048];

    int bid = blockIdx.x;
    int br = bid >> 6;
    int bb = bid & 63;
    const float* xs = (br == 0) ? x1 : (br == 1) ? x2 : x3;
    const float* tp = (br == 0) ? t1 : (br == 1) ? t2 : t3;
    const float* bp = (br == 0) ? b1 : (br == 1) ? b2 : b3;
    int t = threadIdx.x;

    float tv = tp[0];
    float bv = bp[0];

    for (int k = t; k < 1032; k += 256) sA[k] = d_A1sm[br][k];

    const float* xr = xs + bb * 1024;
    #pragma unroll
    for (int kk = 0; kk < 4; kk++) {
        int k = t + kk * 256;
        float xv = xr[k];
        float prod = __fmul_rn(xv, tv);      // no FMA contraction: exact r==b test
        float r = __fsub_rn(bv, prod);
        if (r == bv) r = -10.f;
        sG[k] = __fdividef(1.f, 1.f + __expf(-r));
    }
    if (t < 16) sG[1024 + t] = 0.f;          // zero pad: makes overshoot terms exact zeros
    __syncthreads();

    int qt = t & 127;
    int half = t >> 7;
    float acc[8];
    #pragma unroll
    for (int q = 0; q < 8; q++) acc[q] = 0.f;

    int baseL = qt << 2;
    {
        int N = 1024 - baseL;
        int je_all = (N + 7) & ~7;
        int jm = ((N >> 1) + 7) & ~7;
        corr_loop(sA, sG + baseL, half ? jm : 0, half ? je_all : jm, acc);
    }
    int baseH = 1020 - baseL;
    {
        int N = baseL + 4;
        int je_all = (N + 7) & ~7;
        int jm = ((N >> 1) + 7) & ~7;
        corr_loop(sA, sG + baseH, half ? jm : 0, half ? je_all : jm, acc + 4);
    }

    #pragma unroll
    for (int q = 0; q < 8; q++) sP[q * 256 + t] = acc[q];
    __syncthreads();

    float local = 0.f;
    if (t < 128) {
        #pragma unroll
        for (int q = 0; q < 8; q++) {
            int i = (q < 4) ? (baseL + q) : (baseH + (q - 4));
            float wb1 = sP[q * 256 + t] + sP[q * 256 + t + 128] + d_tail[br][i];
            float act = clamp01(wb1);
            local += d_A2sm[br][i] * (1.f - act);
        }
    }
    __syncthreads();
    sP[t] = local;
    __syncthreads();
    #pragma unroll
    for (int s = 128; s > 0; s >>= 1) {
        if (t < s) sP[t] += sP[t + s];
        __syncthreads();
    }
    if (t == 0) d_S[br][bb] = sP[0];
}

// ---------------------------------------------------------------------------
// Final combine: out[b] = clip(beta4 - sum_br A4sm[br]*(1 - clip(beta_b - S,0,1)),0,1)
// ---------------------------------------------------------------------------
__global__ void final_kernel(const float* __restrict__ bb1p, const float* __restrict__ bb2p,
                             const float* __restrict__ bb3p, const float* __restrict__ beta4p,
                             float* __restrict__ out)
{
    int b = threadIdx.x;
    if (b < BATCH) {
        float acc = beta4p[0];
        float bbv0 = bb1p[0], bbv1 = bb2p[0], bbv2 = bb3p[0];
        float r0 = clamp01(bbv0 - d_S[0][b]);
        float r1 = clamp01(bbv1 - d_S[1][b]);
        float r2 = clamp01(bbv2 - d_S[2][b]);
        acc -= d_A4sm[0] * (1.f - r0);
        acc -= d_A4sm[1] * (1.f - r1);
        acc -= d_A4sm[2] * (1.f - r2);
        out[b] = clamp01(acc);
    }
}

extern "C" void kernel_launch(void* const* d_in, const int* in_sizes, int n_in,
                              void* d_out, int out_size)
{
    const float* x1      = (const float*)d_in[0];
    const float* x2      = (const float*)d_in[1];
    const float* x3      = (const float*)d_in[2];
    const float* t1      = (const float*)d_in[3];
    const float* b1      = (const float*)d_in[4];
    const float* A1_1    = (const float*)d_in[5];
    const float* A2_1    = (const float*)d_in[6];
    const float* beta1_1 = (const float*)d_in[7];
    const float* beta1_2 = (const float*)d_in[8];
    const float* t2      = (const float*)d_in[9];
    const float* b2      = (const float*)d_in[10];
    const float* A1_2    = (const float*)d_in[11];
    const float* A2_2    = (const float*)d_in[12];
    const float* beta2_1 = (const float*)d_in[13];
    const float* beta2_2 = (const float*)d_in[14];
    const float* t3      = (const float*)d_in[15];
    const float* b3      = (const float*)d_in[16];
    const float* A1_3    = (const float*)d_in[17];
    const float* A2_3    = (const float*)d_in[18];
    const float* beta3_1 = (const float*)d_in[19];
    const float* beta3_2 = (const float*)d_in[20];
    const float* A4      = (const float*)d_in[21];
    const float* beta4   = (const float*)d_in[22];
    float* out = (float*)d_out;

    setup_kernel<<<1, 1024>>>(A1_1, A1_2, A1_3, A2_1, A2_2, A2_3, A4,
                              beta1_1, beta2_1, beta3_1);
    corr_kernel<<<192, 256>>>(x1, x2, x3, t1, b1, t2, b2, t3, b3);
    final_kernel<<<1, 64>>>(beta1_2, beta2_2, beta3_2, beta4, out);
}